// round 2
// baseline (speedup 1.0000x reference)
#include <cuda_runtime.h>
#include <cstdint>

#define B_    65536
#define FAN   1024
#define HIDN  512
#define G32   32
#define TB1   128
#define KC    64
#define PITCH 68
#define TB2   128

typedef unsigned long long u64;

__device__ float g_z[(size_t)B_ * G32];   // z scratch [B][32]

__device__ __forceinline__ void ffma2(u64 &d, u64 a, u64 b) {
    asm volatile("fma.rn.f32x2 %0, %1, %2, %0;" : "+l"(d) : "l"(a), "l"(b));
}
__device__ __forceinline__ float lo32(u64 v) { return __uint_as_float((unsigned)(v & 0xffffffffu)); }
__device__ __forceinline__ float hi32(u64 v) { return __uint_as_float((unsigned)(v >> 32)); }

__device__ __forceinline__ float fast_tanh(float x) {
    float e = __expf(-2.f * fabsf(x));
    float t = __fdividef(1.f - e, 1.f + e);
    return copysignf(t, x);
}
__device__ __forceinline__ float fast_sigmoid(float x) {
    return __fdividef(1.f, 1.f + __expf(-x));
}

// ============================================================================
// K1: z[b, g*8+q] = tanh( sum_i comb[b,i]*W1[g,q,i] + b1[g,q] ), comb=[x|h]
// 256 thr: qt=t>>6 (q-group), rta=t&63 (2 rows each). Double-buffered smem.
// ============================================================================
__global__ void __launch_bounds__(256, 2)
k1_gemm1_tanh(const float* __restrict__ x, const float* __restrict__ hst,
              const float* __restrict__ W1, const float* __restrict__ b1)
{
    extern __shared__ float sm[];
    float* combS = sm;                      // [2][TB1][PITCH]
    float* WcS   = sm + 2 * TB1 * PITCH;    // [2][32][PITCH]

    const int t    = threadIdx.x;
    const int qt   = t >> 6;
    const int rta  = t & 63;
    const int row0 = blockIdx.x * TB1;

    float4 pc[8];
    float4 pw[2];

    auto stageLDG = [&](int ch) {
        const int kc = ch * KC;
        const float* src = (kc < 512) ? x : hst;
        const int kbase  = (kc < 512) ? kc : (kc - 512);
        #pragma unroll
        for (int i = 0; i < 8; i++) {
            int flat = i * 256 + t;
            int r = flat >> 4, kq = flat & 15;
            pc[i] = *reinterpret_cast<const float4*>(
                        &src[(size_t)(row0 + r) * 512 + kbase + kq * 4]);
        }
        #pragma unroll
        for (int i = 0; i < 2; i++) {
            int flat = i * 256 + t;
            int q = flat >> 4, kq = flat & 15;
            pw[i] = *reinterpret_cast<const float4*>(&W1[(size_t)q * FAN + kc + kq * 4]);
        }
    };
    auto stageSTS = [&](int buf) {
        #pragma unroll
        for (int i = 0; i < 8; i++) {
            int flat = i * 256 + t;
            int r = flat >> 4, kq = flat & 15;
            *reinterpret_cast<float4*>(&combS[(buf * TB1 + r) * PITCH + kq * 4]) = pc[i];
        }
        #pragma unroll
        for (int i = 0; i < 2; i++) {
            int flat = i * 256 + t;
            int q = flat >> 4, kq = flat & 15;
            *reinterpret_cast<float4*>(&WcS[(buf * 32 + q) * PITCH + kq * 4]) = pw[i];
        }
    };

    u64 acc[2][8];
    #pragma unroll
    for (int r = 0; r < 2; r++)
        #pragma unroll
        for (int j = 0; j < 8; j++) acc[r][j] = 0ull;

    stageLDG(0);
    stageSTS(0);
    __syncthreads();

    for (int ch = 0; ch < 16; ch++) {
        const int buf = ch & 1;
        if (ch + 1 < 16) stageLDG(ch + 1);

        const float* cb = &combS[buf * TB1 * PITCH];
        const float* wb = &WcS[buf * 32 * PITCH];
        #pragma unroll 4
        for (int kq = 0; kq < 16; kq++) {
            ulonglong2 a0 = *reinterpret_cast<const ulonglong2*>(&cb[rta * PITCH + kq * 4]);
            ulonglong2 a1 = *reinterpret_cast<const ulonglong2*>(&cb[(rta + 64) * PITCH + kq * 4]);
            #pragma unroll
            for (int j = 0; j < 8; j++) {
                ulonglong2 wv = *reinterpret_cast<const ulonglong2*>(
                                    &wb[(qt * 8 + j) * PITCH + kq * 4]);
                ffma2(acc[0][j], a0.x, wv.x);
                ffma2(acc[0][j], a0.y, wv.y);
                ffma2(acc[1][j], a1.x, wv.x);
                ffma2(acc[1][j], a1.y, wv.y);
            }
        }
        if (ch + 1 < 16) stageSTS(buf ^ 1);
        __syncthreads();
    }

    float bias[8];
    #pragma unroll
    for (int j = 0; j < 8; j++) bias[j] = b1[qt * 8 + j];

    #pragma unroll
    for (int r = 0; r < 2; r++) {
        const int grow = row0 + rta + r * 64;
        float o[8];
        #pragma unroll
        for (int j = 0; j < 8; j++) {
            float v = lo32(acc[r][j]) + hi32(acc[r][j]) + bias[j];
            o[j] = fast_tanh(v);
        }
        float4* zp = reinterpret_cast<float4*>(&g_z[(size_t)grow * G32 + qt * 8]);
        zp[0] = make_float4(o[0], o[1], o[2], o[3]);
        zp[1] = make_float4(o[4], o[5], o[6], o[7]);
    }
}

// ============================================================================
// K2: gates = sigmoid(z@W2^T + b2); c_new = f*c+i*g; h_new = o*tanh(c_new)
// W2^T+b2 staged as [h][36] in smem; warp-per-row, lane-per-h (coalesced).
// ============================================================================
__global__ void __launch_bounds__(256, 2)
k2_gates_cell(const float* __restrict__ c, const float* __restrict__ W2,
              const float* __restrict__ b2, float* __restrict__ out)
{
    extern __shared__ float sm[];
    float* W2s = sm;                 // [512][36]
    float* zS  = sm + HIDN * 36;     // [TB2][32]

    const int t    = threadIdx.x;
    const int w    = t >> 5;
    const int lane = t & 31;
    const int row0 = blockIdx.x * TB2;

    for (int idx = t; idx < HIDN * G32; idx += 256) {
        int hh = idx >> 5, j = idx & 31;
        int g = j >> 3, q = j & 7;
        W2s[hh * 36 + j] = W2[((size_t)g * HIDN + hh) * 8 + q];
    }
    for (int idx = t; idx < 4 * HIDN; idx += 256) {
        int g = idx >> 9, hh = idx & 511;
        W2s[hh * 36 + 32 + g] = b2[(size_t)g * HIDN + hh];
    }
    #pragma unroll
    for (int i = 0; i < 4; i++) {
        int flat = i * 256 + t;
        int r = flat >> 3, j = flat & 7;
        *reinterpret_cast<float4*>(&zS[r * 32 + j * 4]) =
            *reinterpret_cast<const float4*>(&g_z[(size_t)(row0 + r) * G32 + j * 4]);
    }
    __syncthreads();

    for (int hc = 0; hc < 16; hc++) {
        const int hcol = hc * 32 + lane;

        u64 wu[16];
        #pragma unroll
        for (int j4 = 0; j4 < 8; j4++) {
            ulonglong2 v = *reinterpret_cast<const ulonglong2*>(&W2s[hcol * 36 + j4 * 4]);
            wu[j4 * 2] = v.x; wu[j4 * 2 + 1] = v.y;
        }
        const float4 bias4 = *reinterpret_cast<const float4*>(&W2s[hcol * 36 + 32]);

        float cv_next = c[(size_t)(row0 + w) * HIDN + hcol];

        #pragma unroll 2
        for (int rr = 0; rr < 16; rr++) {
            const int lrow = rr * 8 + w;
            const float cv = cv_next;
            if (rr < 15)
                cv_next = c[(size_t)(row0 + (rr + 1) * 8 + w) * HIDN + hcol];

            u64 zu[16];
            #pragma unroll
            for (int j4 = 0; j4 < 8; j4++) {
                ulonglong2 v = *reinterpret_cast<const ulonglong2*>(&zS[lrow * 32 + j4 * 4]);
                zu[j4 * 2] = v.x; zu[j4 * 2 + 1] = v.y;
            }

            float pre[4];
            #pragma unroll
            for (int g = 0; g < 4; g++) {
                u64 a = 0ull;
                ffma2(a, zu[g * 4 + 0], wu[g * 4 + 0]);
                ffma2(a, zu[g * 4 + 1], wu[g * 4 + 1]);
                ffma2(a, zu[g * 4 + 2], wu[g * 4 + 2]);
                ffma2(a, zu[g * 4 + 3], wu[g * 4 + 3]);
                pre[g] = lo32(a) + hi32(a);
            }

            const float gi = fast_sigmoid(pre[0] + bias4.x);
            const float gf = fast_sigmoid(pre[1] + bias4.y);
            const float go = fast_sigmoid(pre[2] + bias4.z);
            const float gg = fast_sigmoid(pre[3] + bias4.w);

            const float cn = gf * cv + gi * gg;
            const float hn = go * fast_tanh(cn);

            const size_t o = (size_t)(row0 + lrow) * HIDN + hcol;
            out[o] = hn;
            out[(size_t)B_ * HIDN + o] = cn;
        }
    }
}

extern "C" void kernel_launch(void* const* d_in, const int* in_sizes, int n_in,
                              void* d_out, int out_size)
{
    const float* x  = (const float*)d_in[0];
    const float* h  = (const float*)d_in[1];
    const float* c  = (const float*)d_in[2];
    const float* W1 = (const float*)d_in[3];
    const float* b1 = (const float*)d_in[4];
    const float* W2 = (const float*)d_in[5];
    const float* b2 = (const float*)d_in[6];
    float* out = (float*)d_out;

    const int smem1 = (2 * TB1 * PITCH + 2 * 32 * PITCH) * sizeof(float);   // 87040
    const int smem2 = (HIDN * 36 + TB2 * G32) * sizeof(float);              // 90112

    static bool attr_done = false;
    if (!attr_done) {
        cudaFuncSetAttribute(k1_gemm1_tanh, cudaFuncAttributeMaxDynamicSharedMemorySize, smem1);
        cudaFuncSetAttribute(k2_gates_cell, cudaFuncAttributeMaxDynamicSharedMemorySize, smem2);
        attr_done = true;
    }

    k1_gemm1_tanh<<<B_ / TB1, 256, smem1>>>(x, h, W1, b1);
    k2_gates_cell<<<B_ / TB2, 256, smem2>>>(c, W2, b2, out);
}

// round 4
// speedup vs baseline: 1.2644x; 1.2644x over previous
#include <cuda_runtime.h>
#include <cstdint>

#define B_    65536
#define FAN   1024
#define HIDN  512
#define G32   32

// K1 tiling
#define RPC    512     // rows per CTA
#define KC1    16      // k per chunk
#define CPITCH 17      // comb smem pitch (odd -> conflict-free column reads)
#define NCH    64      // 1024 / KC1

// K2 tiling
#define R2     128     // rows per CTA

typedef unsigned long long u64;

__device__ float g_z[(size_t)B_ * G32];   // z scratch [B][32]

__device__ __forceinline__ void ffma2(u64 &d, u64 a, u64 b) {
    asm volatile("fma.rn.f32x2 %0, %1, %2, %0;" : "+l"(d) : "l"(a), "l"(b));
}
__device__ __forceinline__ u64 dup2(float a) {
    u64 r; asm("mov.b64 %0, {%1, %1};" : "=l"(r) : "f"(a)); return r;
}
__device__ __forceinline__ float lo32(u64 v) { return __uint_as_float((unsigned)(v & 0xffffffffu)); }
__device__ __forceinline__ float hi32(u64 v) { return __uint_as_float((unsigned)(v >> 32)); }

__device__ __forceinline__ float tanh_ap(float x) {
    float y; asm("tanh.approx.f32 %0, %1;" : "=f"(y) : "f"(x)); return y;
}
// accurate tanh for K1 (cheap there; keeps error budget for K2's approx)
__device__ __forceinline__ float tanh_acc(float x) {
    float e = __expf(-2.f * fabsf(x));
    float t = __fdividef(1.f - e, 1.f + e);
    return copysignf(t, x);
}

// ============================================================================
// K1: z[b, j] = tanh( sum_k comb[b,k]*W1[j,k] + b1[j] ),  j = g*8+q in 0..31
// Thread <-> row mapping: 256 threads, rows t and t+256 of a 512-row tile.
// Accumulators f32x2-packed along j (16 u64 per row). W chunk in smem is read
// as full-warp BROADCAST (no crossbar cost); comb column reads are scalar LDS
// with odd pitch (conflict-free). Double-buffered chunks of K=16.
// ============================================================================
__global__ void __launch_bounds__(256, 1)
k1_gemm1_tanh(const float* __restrict__ x, const float* __restrict__ hst,
              const float* __restrict__ W1, const float* __restrict__ b1)
{
    extern __shared__ float sm[];
    float* combS = sm;                       // [2][RPC][CPITCH]
    float* wS    = sm + 2 * RPC * CPITCH;    // [2][KC1][32]

    const int t    = threadIdx.x;
    const int row0 = blockIdx.x * RPC;

    float4 pc[8];
    float4 pw;

    auto stageLDG = [&](int ch) {
        const int kb = ch * KC1;
        const float* src = (kb < 512) ? x : hst;
        const int kcol   = (kb < 512) ? kb : kb - 512;
        #pragma unroll
        for (int i = 0; i < 8; i++) {
            int flat = i * 256 + t;          // 0..2047 float4s (512 rows x 4)
            int r = flat >> 2, kq = flat & 3;
            pc[i] = *reinterpret_cast<const float4*>(
                        &src[(size_t)(row0 + r) * 512 + kcol + kq * 4]);
        }
        if (t < 128) {
            int j = t >> 2, kq = t & 3;      // j 0..31, kq 0..3
            pw = *reinterpret_cast<const float4*>(&W1[(size_t)j * FAN + kb + kq * 4]);
        }
    };
    auto stageSTS = [&](int buf) {
        float* cb = combS + buf * RPC * CPITCH;
        #pragma unroll
        for (int i = 0; i < 8; i++) {
            int flat = i * 256 + t;
            int r = flat >> 2, kq = flat & 3;
            float* d = &cb[r * CPITCH + kq * 4];
            d[0] = pc[i].x; d[1] = pc[i].y; d[2] = pc[i].z; d[3] = pc[i].w;
        }
        if (t < 128) {
            int j = t >> 2, kq = t & 3;
            float* wb = wS + buf * KC1 * 32;
            wb[(kq * 4 + 0) * 32 + j] = pw.x;
            wb[(kq * 4 + 1) * 32 + j] = pw.y;
            wb[(kq * 4 + 2) * 32 + j] = pw.z;
            wb[(kq * 4 + 3) * 32 + j] = pw.w;
        }
    };

    u64 acc0[16], acc1[16];
    #pragma unroll
    for (int p = 0; p < 16; p++) { acc0[p] = 0ull; acc1[p] = 0ull; }

    stageLDG(0);
    stageSTS(0);
    __syncthreads();

    for (int ch = 0; ch < NCH; ch++) {
        const int buf = ch & 1;
        if (ch + 1 < NCH) stageLDG(ch + 1);

        const float* cb = combS + buf * RPC * CPITCH;
        const float* wb = wS    + buf * KC1 * 32;
        #pragma unroll
        for (int k = 0; k < KC1; k++) {
            const u64 A0 = dup2(cb[t * CPITCH + k]);
            const u64 A1 = dup2(cb[(t + 256) * CPITCH + k]);
            const ulonglong2* wp = reinterpret_cast<const ulonglong2*>(&wb[k * 32]);
            #pragma unroll
            for (int p = 0; p < 8; p++) {
                ulonglong2 wv = wp[p];           // broadcast LDS.128
                ffma2(acc0[2 * p],     A0, wv.x);
                ffma2(acc0[2 * p + 1], A0, wv.y);
                ffma2(acc1[2 * p],     A1, wv.x);
                ffma2(acc1[2 * p + 1], A1, wv.y);
            }
        }
        if (ch + 1 < NCH) stageSTS((ch + 1) & 1);
        __syncthreads();
    }

    // epilogue: bias + tanh, one full z-row per thread-row
    float bias[32];
    #pragma unroll
    for (int j = 0; j < 32; j++) bias[j] = __ldg(&b1[j]);

    #pragma unroll
    for (int rr = 0; rr < 2; rr++) {
        const u64* ac = rr ? acc1 : acc0;
        const int grow = row0 + t + rr * 256;
        float o[32];
        #pragma unroll
        for (int p = 0; p < 16; p++) {
            o[2 * p]     = tanh_acc(lo32(ac[p]) + bias[2 * p]);
            o[2 * p + 1] = tanh_acc(hi32(ac[p]) + bias[2 * p + 1]);
        }
        float4* zp = reinterpret_cast<float4*>(&g_z[(size_t)grow * G32]);
        #pragma unroll
        for (int v = 0; v < 8; v++)
            zp[v] = make_float4(o[4 * v], o[4 * v + 1], o[4 * v + 2], o[4 * v + 3]);
    }
}

// ============================================================================
// K2: gates = sigmoid(z@W2^T + b2); c_new = f*c+i*g; h_new = o*tanh(c_new)
// Thread <-> h-column: 512 threads, W2^T[h][32] lives in 16 u64 REGISTERS for
// the whole kernel. z rows broadcast from smem. c loads & out stores coalesced.
// sigmoid via MUFU.TANH: sigma(x) = 0.5*tanh(0.5x)+0.5  (5 MUFU / point).
// ============================================================================
__global__ void __launch_bounds__(512, 1)
k2_gates_cell(const float* __restrict__ c, const float* __restrict__ W2,
              const float* __restrict__ b2, float* __restrict__ out)
{
    __shared__ float zS[R2 * G32];           // 16 KB

    const int t    = threadIdx.x;            // == h column
    const int row0 = blockIdx.x * R2;

    // W2^T + half-bias into registers (coalesced 32B per thread per gate)
    u64 wu[16];
    float bh[4];
    #pragma unroll
    for (int g = 0; g < 4; g++) {
        const ulonglong2* p = reinterpret_cast<const ulonglong2*>(
                                  &W2[((size_t)g * HIDN + t) * 8]);
        ulonglong2 v0 = p[0], v1 = p[1];
        wu[g * 4 + 0] = v0.x; wu[g * 4 + 1] = v0.y;
        wu[g * 4 + 2] = v1.x; wu[g * 4 + 3] = v1.y;
        bh[g] = 0.5f * __ldg(&b2[(size_t)g * HIDN + t]);
    }

    // stage z tile [R2][32] (coalesced)
    #pragma unroll
    for (int i = 0; i < 2; i++) {
        int flat = i * 512 + t;              // 0..1023 float4s
        *reinterpret_cast<float4*>(&zS[flat * 4]) =
            *reinterpret_cast<const float4*>(&g_z[(size_t)row0 * G32 + flat * 4]);
    }
    __syncthreads();

    const float* cp = c   + (size_t)row0 * HIDN + t;
    float*       o1 = out + (size_t)row0 * HIDN + t;
    float*       o2 = o1  + (size_t)B_ * HIDN;

    float cnext = cp[0];
    #pragma unroll 4
    for (int r = 0; r < R2; r++) {
        const float cv = cnext;
        if (r < R2 - 1) cnext = cp[(size_t)(r + 1) * HIDN];

        const ulonglong2* zp = reinterpret_cast<const ulonglong2*>(&zS[r * G32]);
        float pre[4];
        #pragma unroll
        for (int g = 0; g < 4; g++) {
            ulonglong2 z0 = zp[2 * g], z1 = zp[2 * g + 1];   // broadcast LDS.128
            u64 a = 0ull;
            ffma2(a, z0.x, wu[g * 4 + 0]);
            ffma2(a, z0.y, wu[g * 4 + 1]);
            ffma2(a, z1.x, wu[g * 4 + 2]);
            ffma2(a, z1.y, wu[g * 4 + 3]);
            pre[g] = lo32(a) + hi32(a);
        }

        const float gi = fmaf(0.5f, tanh_ap(fmaf(0.5f, pre[0], bh[0])), 0.5f);
        const float gf = fmaf(0.5f, tanh_ap(fmaf(0.5f, pre[1], bh[1])), 0.5f);
        const float go = fmaf(0.5f, tanh_ap(fmaf(0.5f, pre[2], bh[2])), 0.5f);
        const float gg = fmaf(0.5f, tanh_ap(fmaf(0.5f, pre[3], bh[3])), 0.5f);

        const float cn = fmaf(gf, cv, gi * gg);
        const float hn = go * tanh_ap(cn);

        o1[(size_t)r * HIDN] = hn;
        o2[(size_t)r * HIDN] = cn;
    }
}

extern "C" void kernel_launch(void* const* d_in, const int* in_sizes, int n_in,
                              void* d_out, int out_size)
{
    const float* x  = (const float*)d_in[0];
    const float* h  = (const float*)d_in[1];
    const float* c  = (const float*)d_in[2];
    const float* W1 = (const float*)d_in[3];
    const float* b1 = (const float*)d_in[4];
    const float* W2 = (const float*)d_in[5];
    const float* b2 = (const float*)d_in[6];
    float* out = (float*)d_out;

    const int smem1 = (2 * RPC * CPITCH + 2 * KC1 * 32) * sizeof(float);  // 73728

    static bool attr_done = false;
    if (!attr_done) {
        cudaFuncSetAttribute(k1_gemm1_tanh, cudaFuncAttributeMaxDynamicSharedMemorySize, smem1);
        attr_done = true;
    }

    k1_gemm1_tanh<<<B_ / RPC, 256, smem1>>>(x, h, W1, b1);
    k2_gates_cell<<<B_ / R2, 512>>>(c, W2, b2, out);
}